// round 5
// baseline (speedup 1.0000x reference)
#include <cuda_runtime.h>
#include <stdint.h>
#include <math.h>

#define Bdim 4
#define Ndim 2048
#define Ddim 1024
#define Hdim 8
#define Edim 16
#define CSdim 2048
#define Rdim (Bdim*Ndim)   /* 8192 rows */
#define Jdim (Hdim*Edim)   /* 128 projection outputs per row */

// Borderline threshold: flag (row,head) where top-2 gap <= TAU * ||y||.
#define TAU 1e-3f

// ---------------- device scratch (no allocations allowed) ----------------
__device__ float g_Wt[Ddim*Jdim];                 // transposed projs [d][j]  (512KB)
__device__ float g_S[Jdim];                       // column sums of Wt
__device__ float g_cbi[Hdim*(CSdim/2)*(2*Edim)];  // normalized codebook, pair-interleaved (1MB)
__device__ float g_Y[Rdim*Jdim];                  // projections after mean-subtract (4MB)
__device__ int   g_flag[Rdim*Hdim];               // borderline flags (256KB)

typedef unsigned long long u64;

__device__ __forceinline__ u64 pack2(float lo, float hi) {
    u64 r; asm("mov.b64 %0,{%1,%2};" : "=l"(r) : "f"(lo), "f"(hi)); return r;
}
__device__ __forceinline__ void unpack2(float& lo, float& hi, u64 v) {
    asm("mov.b64 {%0,%1},%2;" : "=f"(lo), "=f"(hi) : "l"(v));
}
__device__ __forceinline__ u64 ffma2(u64 a, u64 b, u64 c) {
    u64 d; asm("fma.rn.f32x2 %0,%1,%2,%3;" : "=l"(d) : "l"(a), "l"(b), "l"(c)); return d;
}
__device__ __forceinline__ u64 fadd2(u64 a, u64 b) {
    u64 d; asm("add.rn.f32x2 %0,%1,%2;" : "=l"(d) : "l"(a), "l"(b)); return d;
}

// ---------------- prep 1: transpose rand_projs [h,d,e] -> Wt[d][j], j=h*16+e ----
__global__ void kTranspose(const float* __restrict__ W) {
    int idx = blockIdx.x * 256 + threadIdx.x;
    if (idx < Ddim * Jdim) {
        int d = idx >> 7, j = idx & 127;
        g_Wt[idx] = W[(j >> 4) * (Ddim * Edim) + d * Edim + (j & 15)];
    }
}

// ---------------- prep 2: S[j] = sum_d Wt[d][j] -------------------------------
__global__ void kColsum() {
    int j = threadIdx.x;  // 128 threads
    float s = 0.f;
    for (int d = 0; d < Ddim; d++) s += g_Wt[d * Jdim + j];
    g_S[j] = s;
}

// ---------------- prep 3: L2-normalize codebook, interleave pairs -------------
__global__ void kCb(const float* __restrict__ cbk) {
    int idx = blockIdx.x * 256 + threadIdx.x;
    if (idx < Hdim * CSdim) {
        const float* row = cbk + (size_t)idx * Edim;
        float v[Edim];
        float ss = 0.f;
#pragma unroll
        for (int e = 0; e < Edim; e++) { v[e] = row[e]; ss += v[e] * v[e]; }
        float inv = 1.0f / sqrtf(ss + 1e-12f);
        int h = idx / CSdim, c = idx % CSdim;
        float* dst = g_cbi + h * (CSdim / 2) * 32 + (c >> 1) * 32 + (c & 1);
#pragma unroll
        for (int e = 0; e < Edim; e++) dst[e * 2] = v[e] * inv;
    }
}

// ---------------- kernel Y: Y = X @ Wt - mu * S  (64x128 tile SGEMM) ----------
__global__ __launch_bounds__(256) void kernY(const float* __restrict__ x) {
    __shared__ __align__(16) float Xs[16][68];
    __shared__ __align__(16) float Wsm[16][128];
    __shared__ float Ssm[128];
    __shared__ float redsum[256];
    __shared__ float mus[64];

    int tid = threadIdx.x;
    int row0 = blockIdx.x * 64;
    if (tid < 128) Ssm[tid] = g_S[tid];

    int tx = tid & 15, ty = tid >> 4;
    int ldr = tid >> 2, ldc = (tid & 3) * 4;
    int wr  = tid >> 4, wc  = (tid & 15) * 8;

    u64 acc[4][4];
#pragma unroll
    for (int i = 0; i < 4; i++)
#pragma unroll
        for (int p = 0; p < 4; p++) acc[i][p] = 0ull;

    float psum = 0.f;

    for (int kc = 0; kc < Ddim / 16; kc++) {
        int k0 = kc * 16;
        float4 xv  = *(const float4*)(x + (size_t)(row0 + ldr) * Ddim + k0 + ldc);
        float4 wv0 = *(const float4*)(g_Wt + (size_t)(k0 + wr) * Jdim + wc);
        float4 wv1 = *(const float4*)(g_Wt + (size_t)(k0 + wr) * Jdim + wc + 4);
        psum += xv.x + xv.y + xv.z + xv.w;

        __syncthreads();
        Xs[ldc + 0][ldr] = xv.x;
        Xs[ldc + 1][ldr] = xv.y;
        Xs[ldc + 2][ldr] = xv.z;
        Xs[ldc + 3][ldr] = xv.w;
        *(float4*)&Wsm[wr][wc]     = wv0;
        *(float4*)&Wsm[wr][wc + 4] = wv1;
        __syncthreads();

#pragma unroll
        for (int k = 0; k < 16; k++) {
            float4 av = *(const float4*)&Xs[k][ty * 4];
            u64 a0 = pack2(av.x, av.x);
            u64 a1 = pack2(av.y, av.y);
            u64 a2 = pack2(av.z, av.z);
            u64 a3 = pack2(av.w, av.w);
#pragma unroll
            for (int p = 0; p < 4; p++) {
                u64 b = *(const u64*)&Wsm[k][p * 32 + tx * 2];
                acc[0][p] = ffma2(a0, b, acc[0][p]);
                acc[1][p] = ffma2(a1, b, acc[1][p]);
                acc[2][p] = ffma2(a2, b, acc[2][p]);
                acc[3][p] = ffma2(a3, b, acc[3][p]);
            }
        }
    }

    redsum[tid] = psum;
    __syncthreads();
    if (tid < 64)
        mus[tid] = (redsum[4 * tid] + redsum[4 * tid + 1] +
                    redsum[4 * tid + 2] + redsum[4 * tid + 3]) * (1.0f / Ddim);
    __syncthreads();

#pragma unroll
    for (int i = 0; i < 4; i++) {
        int r = row0 + ty * 4 + i;
        float mu = mus[ty * 4 + i];
#pragma unroll
        for (int p = 0; p < 4; p++) {
            int n0 = p * 32 + tx * 2;
            float lo, hi;
            unpack2(lo, hi, acc[i][p]);
            lo -= mu * Ssm[n0];
            hi -= mu * Ssm[n0 + 1];
            float2 v = make_float2(lo, hi);
            *(float2*)(g_Y + (size_t)r * Jdim + n0) = v;
        }
    }
}

// ---------------- kernel S: sims + top-2 argmax per (row, head) ---------------
__global__ __launch_bounds__(256) void kernS(float* __restrict__ out) {
    __shared__ __align__(16) float scb[128 * 32];   // 16KB: 128 code-pairs
    __shared__ float sv1[8][32][2];
    __shared__ float sv2[8][32][2];
    __shared__ int   six[8][32][2];

    int tid = threadIdx.x;
    int lane = tid & 31, warp = tid >> 5;
    int h = blockIdx.y;
    int row0 = blockIdx.x * 64;
    int r0 = row0 + 2 * lane;

    u64 y2[2][Edim];
    float ynorm[2];
#pragma unroll
    for (int rr = 0; rr < 2; rr++) {
        const float* yp = g_Y + (size_t)(r0 + rr) * Jdim + h * Edim;
        float n2 = 0.f;
#pragma unroll
        for (int e4 = 0; e4 < 4; e4++) {
            float4 v = *(const float4*)(yp + e4 * 4);
            n2 += v.x*v.x + v.y*v.y + v.z*v.z + v.w*v.w;
            y2[rr][e4 * 4 + 0] = pack2(v.x, v.x);
            y2[rr][e4 * 4 + 1] = pack2(v.y, v.y);
            y2[rr][e4 * 4 + 2] = pack2(v.z, v.z);
            y2[rr][e4 * 4 + 3] = pack2(v.w, v.w);
        }
        ynorm[rr] = sqrtf(n2);
    }

    const float NEGINF = __int_as_float(0xff800000u);
    float bv1[2] = {NEGINF, NEGINF}, bv2[2] = {NEGINF, NEGINF};
    int   bix[2] = {0, 0};

    const float4* src = (const float4*)(g_cbi + (size_t)h * (CSdim / 2) * 32);

    for (int ch = 0; ch < 8; ch++) {                 // 8 chunks of 128 code-pairs
        __syncthreads();
        for (int t = tid; t < 128 * 32 / 4; t += 256)
            ((float4*)scb)[t] = src[ch * (128 * 32 / 4) + t];
        __syncthreads();

#pragma unroll 2
        for (int t = 0; t < 16; t++) {
            int cpl = warp * 16 + t;
            int cp = ch * 128 + cpl;                 // ascending per warp
            const u64* cb = (const u64*)(scb + cpl * 32);
            u64 a0 = 0ull, a1 = 0ull, b0 = 0ull, b1 = 0ull;
#pragma unroll
            for (int e = 0; e < 8; e++) {
                u64 c2 = cb[e];
                a0 = ffma2(y2[0][e], c2, a0);
                a1 = ffma2(y2[1][e], c2, a1);
            }
#pragma unroll
            for (int e = 8; e < 16; e++) {
                u64 c2 = cb[e];
                b0 = ffma2(y2[0][e], c2, b0);
                b1 = ffma2(y2[1][e], c2, b1);
            }
            u64 s0 = fadd2(a0, b0), s1 = fadd2(a1, b1);
            int c0 = 2 * cp;
            float xlo, xhi;
            unpack2(xlo, xhi, s0);
            if (xlo > bv1[0]) { bv2[0] = bv1[0]; bv1[0] = xlo; bix[0] = c0; }
            else if (xlo > bv2[0]) bv2[0] = xlo;
            if (xhi > bv1[0]) { bv2[0] = bv1[0]; bv1[0] = xhi; bix[0] = c0 + 1; }
            else if (xhi > bv2[0]) bv2[0] = xhi;
            unpack2(xlo, xhi, s1);
            if (xlo > bv1[1]) { bv2[1] = bv1[1]; bv1[1] = xlo; bix[1] = c0; }
            else if (xlo > bv2[1]) bv2[1] = xlo;
            if (xhi > bv1[1]) { bv2[1] = bv1[1]; bv1[1] = xhi; bix[1] = c0 + 1; }
            else if (xhi > bv2[1]) bv2[1] = xhi;
        }
    }

#pragma unroll
    for (int rr = 0; rr < 2; rr++) {
        sv1[warp][lane][rr] = bv1[rr];
        sv2[warp][lane][rr] = bv2[rr];
        six[warp][lane][rr] = bix[rr];
    }
    __syncthreads();

    if (warp == 0) {
#pragma unroll
        for (int rr = 0; rr < 2; rr++) {
            const float NEGINF2 = __int_as_float(0xff800000u);
            float v1 = NEGINF2, v2 = NEGINF2;
            int i1 = 0;
#pragma unroll
            for (int w = 0; w < 8; w++) {
                float a = sv1[w][lane][rr];
                int  ia = six[w][lane][rr];
                float b = sv2[w][lane][rr];
                if (a > v1 || (a == v1 && ia < i1)) {
                    v2 = fmaxf(v2, v1); v1 = a; i1 = ia;
                } else {
                    v2 = fmaxf(v2, a);
                }
                v2 = fmaxf(v2, b);
            }
            int id = (r0 + rr) * Hdim + h;
            out[id] = (float)i1;
            g_flag[id] = (v1 - v2) <= TAU * ynorm[rr] ? 1 : 0;
        }
    }
}

// ---------------- kernel Fix: fp64 recompute for borderline cases -------------
// One warp per (row, head). Non-flagged warps exit immediately.
// Grid MUST cover all Rdim*Hdim = 65536 cases: 8192 blocks x 8 warps.
__global__ __launch_bounds__(256) void kFix(const float* __restrict__ x,
                                            const float* __restrict__ W,
                                            const float* __restrict__ cbk,
                                            float* __restrict__ out) {
    int wid = blockIdx.x * 8 + (threadIdx.x >> 5);   // case id in [0, Rdim*Hdim)
    int lane = threadIdx.x & 31;
    if (!g_flag[wid]) return;

    int row = wid >> 3, h = wid & 7;
    const float* xr = x + (size_t)row * Ddim;

    // fp64 mean of the row
    double s = 0.0;
#pragma unroll 4
    for (int k = 0; k < 32; k++) s += (double)xr[32 * k + lane];
#pragma unroll
    for (int o = 16; o; o >>= 1) s += __shfl_xor_sync(0xffffffffu, s, o);
    double mu = s * (1.0 / 1024.0);

    // fp64 projections p[e] = sum_d (x_d - mu) * W[h][d][e]
    // (sigma scale and q-normalization are positive per-row scalars -> dropped)
    double acc[Edim];
#pragma unroll
    for (int e = 0; e < Edim; e++) acc[e] = 0.0;
    const float* Wh = W + (size_t)h * (Ddim * Edim);
    for (int k = 0; k < 32; k++) {
        int d = 32 * k + lane;
        double xv = (double)xr[d] - mu;
        const float* wp = Wh + d * Edim;
#pragma unroll
        for (int e = 0; e < Edim; e++) acc[e] += xv * (double)wp[e];
    }
#pragma unroll
    for (int e = 0; e < Edim; e++) {
#pragma unroll
        for (int o = 16; o; o >>= 1)
            acc[e] += __shfl_xor_sync(0xffffffffu, acc[e], o);
    }

    // fp64 sims over all codes, argmax with first-max semantics
    const float* cbh = cbk + (size_t)h * (CSdim * Edim);
    double bv = -1.0e300;
    int bi = 0;
    for (int c = lane; c < CSdim; c += 32) {          // ascending per lane
        const float* cp_ = cbh + c * Edim;
        double dot = 0.0, nn = 0.0;
#pragma unroll
        for (int e = 0; e < Edim; e++) {
            double cv = (double)cp_[e];
            dot += acc[e] * cv;
            nn  += cv * cv;
        }
        double sv = dot / sqrt(nn + 1e-12);
        if (sv > bv) { bv = sv; bi = c; }
    }
#pragma unroll
    for (int o = 16; o; o >>= 1) {
        double ov = __shfl_xor_sync(0xffffffffu, bv, o);
        int    oi = __shfl_xor_sync(0xffffffffu, bi, o);
        if (ov > bv || (ov == bv && oi < bi)) { bv = ov; bi = oi; }
    }
    if (lane == 0) out[(size_t)row * Hdim + h] = (float)bi;
}

// ---------------- launch ------------------------------------------------------
extern "C" void kernel_launch(void* const* d_in, const int* in_sizes, int n_in,
                              void* d_out, int out_size) {
    const float* x   = (const float*)d_in[0];
    const float* W   = (n_in > 1) ? (const float*)d_in[1] : nullptr;
    const float* cbk = (n_in > 2) ? (const float*)d_in[2] : nullptr;
    for (int i = 0; i < n_in; i++) {
        if      (in_sizes[i] == Rdim * Ddim)         x   = (const float*)d_in[i];
        else if (in_sizes[i] == Hdim * Ddim * Edim)  W   = (const float*)d_in[i];
        else if (in_sizes[i] == Hdim * CSdim * Edim) cbk = (const float*)d_in[i];
    }
    float* out = (float*)d_out;   // [4,2048,8] indices stored as float32

    kTranspose<<<(Ddim * Jdim + 255) / 256, 256>>>(W);
    kColsum<<<1, 128>>>();
    kCb<<<(Hdim * CSdim + 255) / 256, 256>>>(cbk);

    kernY<<<Rdim / 64, 256>>>(x);

    dim3 gs(Rdim / 64, Hdim);
    kernS<<<gs, 256>>>(out);

    // 65536 cases / 8 warps per block = 8192 blocks (previous round's grid
    // only covered 256 cases -- the fixup never touched the flipped entries)
    kFix<<<Rdim * Hdim / 8, 256>>>(x, W, cbk, out);
}

// round 6
// speedup vs baseline: 1.0781x; 1.0781x over previous
#include <cuda_runtime.h>
#include <stdint.h>
#include <math.h>

#define Bdim 4
#define Ndim 2048
#define Ddim 1024
#define Hdim 8
#define Edim 16
#define CSdim 2048
#define Rdim (Bdim*Ndim)   /* 8192 rows */
#define Jdim (Hdim*Edim)   /* 128 projection outputs per row */

// Borderline threshold: flag (row,head) where top-2 gap <= TAU * ||y||.
#define TAU 1e-3f

// ---------------- device scratch (no allocations allowed) ----------------
__device__ float g_Wt[Ddim*Jdim];                 // transposed projs [d][j]  (512KB)
__device__ float g_S[Jdim];                       // column sums of Wt
__device__ float g_cbi[Hdim*(CSdim/2)*(2*Edim)];  // normalized codebook, pair-interleaved (1MB)
__device__ float g_Y[Rdim*Jdim];                  // projections after mean-subtract (4MB)
__device__ int   g_list[Rdim*Hdim];               // compact worklist of borderline cases
__device__ int   g_cnt;                           // worklist counter

typedef unsigned long long u64;

__device__ __forceinline__ u64 pack2(float lo, float hi) {
    u64 r; asm("mov.b64 %0,{%1,%2};" : "=l"(r) : "f"(lo), "f"(hi)); return r;
}
__device__ __forceinline__ void unpack2(float& lo, float& hi, u64 v) {
    asm("mov.b64 {%0,%1},%2;" : "=f"(lo), "=f"(hi) : "l"(v));
}
__device__ __forceinline__ u64 ffma2(u64 a, u64 b, u64 c) {
    u64 d; asm("fma.rn.f32x2 %0,%1,%2,%3;" : "=l"(d) : "l"(a), "l"(b), "l"(c)); return d;
}
__device__ __forceinline__ u64 fadd2(u64 a, u64 b) {
    u64 d; asm("add.rn.f32x2 %0,%1,%2;" : "=l"(d) : "l"(a), "l"(b)); return d;
}

// ---------------- prep 1: transpose rand_projs -> Wt[d][j]; zero worklist -----
__global__ void kTranspose(const float* __restrict__ W) {
    if (blockIdx.x == 0 && threadIdx.x == 0) g_cnt = 0;
    int idx = blockIdx.x * 256 + threadIdx.x;
    if (idx < Ddim * Jdim) {
        int d = idx >> 7, j = idx & 127;
        g_Wt[idx] = W[(j >> 4) * (Ddim * Edim) + d * Edim + (j & 15)];
    }
}

// ---------------- prep 2: S[j] = sum_d Wt[d][j]  (1024 thr, 8-way split) ------
__global__ void kColsum() {
    __shared__ float part[1024];
    int tid = threadIdx.x;
    int j = tid & 127, seg = tid >> 7;       // 8 segments of 128 d each
    float s = 0.f;
    int d0 = seg * 128;
#pragma unroll 8
    for (int d = 0; d < 128; d++) s += g_Wt[(d0 + d) * Jdim + j];
    part[tid] = s;
    __syncthreads();
    if (tid < 128) {
        float t = 0.f;
#pragma unroll
        for (int g = 0; g < 8; g++) t += part[g * 128 + tid];
        g_S[tid] = t;
    }
}

// ---------------- prep 3: L2-normalize codebook, interleave pairs -------------
__global__ void kCb(const float* __restrict__ cbk) {
    int idx = blockIdx.x * 256 + threadIdx.x;
    if (idx < Hdim * CSdim) {
        const float* row = cbk + (size_t)idx * Edim;
        float v[Edim];
        float ss = 0.f;
#pragma unroll
        for (int e = 0; e < Edim; e++) { v[e] = row[e]; ss += v[e] * v[e]; }
        float inv = 1.0f / sqrtf(ss + 1e-12f);
        int h = idx / CSdim, c = idx % CSdim;
        float* dst = g_cbi + h * (CSdim / 2) * 32 + (c >> 1) * 32 + (c & 1);
#pragma unroll
        for (int e = 0; e < Edim; e++) dst[e * 2] = v[e] * inv;
    }
}

// ---------------- kernel Y: Y = X @ Wt - mu * S  (32x128 tile, grid 256) ------
__global__ __launch_bounds__(256) void kernY(const float* __restrict__ x) {
    __shared__ __align__(16) float Xs[16][36];     // [k][m=32], padded
    __shared__ __align__(16) float Wsm[16][128];   // [k][n]
    __shared__ float Ssm[128];
    __shared__ float redsum[128];
    __shared__ float mus[32];

    int tid = threadIdx.x;
    int row0 = blockIdx.x * 32;
    if (tid < 128) Ssm[tid] = g_S[tid];

    int tx = tid & 15, ty = tid >> 4;          // compute: rows ty*2+{0,1}, col-pairs p*32+tx*2
    int ldr = tid >> 2, ldc = (tid & 3) * 4;   // X loader (threads 0..127)
    int wr  = tid >> 4, wc  = (tid & 15) * 8;  // W loader (all 256)

    u64 acc[2][4];
#pragma unroll
    for (int i = 0; i < 2; i++)
#pragma unroll
        for (int p = 0; p < 4; p++) acc[i][p] = 0ull;

    float psum = 0.f;

    for (int kc = 0; kc < Ddim / 16; kc++) {
        int k0 = kc * 16;
        float4 xv = make_float4(0.f, 0.f, 0.f, 0.f);
        if (tid < 128)
            xv = *(const float4*)(x + (size_t)(row0 + ldr) * Ddim + k0 + ldc);
        float4 wv0 = *(const float4*)(g_Wt + (size_t)(k0 + wr) * Jdim + wc);
        float4 wv1 = *(const float4*)(g_Wt + (size_t)(k0 + wr) * Jdim + wc + 4);
        psum += xv.x + xv.y + xv.z + xv.w;

        __syncthreads();
        if (tid < 128) {
            Xs[ldc + 0][ldr] = xv.x;
            Xs[ldc + 1][ldr] = xv.y;
            Xs[ldc + 2][ldr] = xv.z;
            Xs[ldc + 3][ldr] = xv.w;
        }
        *(float4*)&Wsm[wr][wc]     = wv0;
        *(float4*)&Wsm[wr][wc + 4] = wv1;
        __syncthreads();

#pragma unroll
        for (int k = 0; k < 16; k++) {
            float a0s = Xs[k][ty * 2 + 0];
            float a1s = Xs[k][ty * 2 + 1];
            u64 a0 = pack2(a0s, a0s);
            u64 a1 = pack2(a1s, a1s);
#pragma unroll
            for (int p = 0; p < 4; p++) {
                u64 b = *(const u64*)&Wsm[k][p * 32 + tx * 2];
                acc[0][p] = ffma2(a0, b, acc[0][p]);
                acc[1][p] = ffma2(a1, b, acc[1][p]);
            }
        }
    }

    if (tid < 128) redsum[tid] = psum;
    __syncthreads();
    if (tid < 32)
        mus[tid] = (redsum[4 * tid] + redsum[4 * tid + 1] +
                    redsum[4 * tid + 2] + redsum[4 * tid + 3]) * (1.0f / Ddim);
    __syncthreads();

#pragma unroll
    for (int i = 0; i < 2; i++) {
        int lr = ty * 2 + i;
        int r = row0 + lr;
        float mu = mus[lr];
#pragma unroll
        for (int p = 0; p < 4; p++) {
            int n0 = p * 32 + tx * 2;
            float lo, hi;
            unpack2(lo, hi, acc[i][p]);
            lo -= mu * Ssm[n0];
            hi -= mu * Ssm[n0 + 1];
            *(float2*)(g_Y + (size_t)r * Jdim + n0) = make_float2(lo, hi);
        }
    }
}

// ---------------- kernel S: sims + branchless top-2 argmax --------------------
// CTA = 64 rows x 1 head, 256 threads. Double-buffered 16KB codebook chunks.
// warp = code subset (broadcast LDS64), lane = row-pair.
__global__ __launch_bounds__(256, 2) void kernS(float* __restrict__ out) {
    __shared__ __align__(16) float buf[2][128 * 32];  // 2 x 16KB chunk buffers
    __shared__ float sv1[8][32][2];
    __shared__ float sv2[8][32][2];
    __shared__ int   six[8][32][2];

    int tid = threadIdx.x;
    int lane = tid & 31, warp = tid >> 5;
    int h = blockIdx.y;
    int row0 = blockIdx.x * 64;
    int r0 = row0 + 2 * lane;

    // y duplicated into f32x2 registers for both rows of this lane's pair
    u64 y2[2][Edim];
    float ynorm[2];
#pragma unroll
    for (int rr = 0; rr < 2; rr++) {
        const float* yp = g_Y + (size_t)(r0 + rr) * Jdim + h * Edim;
        float n2 = 0.f;
#pragma unroll
        for (int e4 = 0; e4 < 4; e4++) {
            float4 v = *(const float4*)(yp + e4 * 4);
            n2 += v.x*v.x + v.y*v.y + v.z*v.z + v.w*v.w;
            y2[rr][e4 * 4 + 0] = pack2(v.x, v.x);
            y2[rr][e4 * 4 + 1] = pack2(v.y, v.y);
            y2[rr][e4 * 4 + 2] = pack2(v.z, v.z);
            y2[rr][e4 * 4 + 3] = pack2(v.w, v.w);
        }
        ynorm[rr] = sqrtf(n2);
    }

    const float NEGINF = __int_as_float(0xff800000u);
    float bv1_0 = NEGINF, bv2_0 = NEGINF, bv1_1 = NEGINF, bv2_1 = NEGINF;
    int bi0 = 0, bi1 = 0;

    const float4* src = (const float4*)(g_cbi + (size_t)h * (CSdim / 2) * 32);

    // preload chunk 0
#pragma unroll
    for (int i = 0; i < 4; i++)
        ((float4*)buf[0])[tid + 256 * i] = src[tid + 256 * i];
    __syncthreads();

    for (int ch = 0; ch < 8; ch++) {
        int pb = ch & 1;
        float4 pf0, pf1, pf2, pf3;
        if (ch < 7) {                                // prefetch next chunk into regs
            const float4* s2 = src + (ch + 1) * 1024;
            pf0 = s2[tid];       pf1 = s2[tid + 256];
            pf2 = s2[tid + 512]; pf3 = s2[tid + 768];
        }

#pragma unroll 2
        for (int t = 0; t < 16; t++) {
            int cpl = warp * 16 + t;
            int cp = ch * 128 + cpl;                 // ascending per warp
            const u64* cb = (const u64*)(buf[pb] + cpl * 32);
            u64 a0 = 0ull, a1 = 0ull, b0 = 0ull, b1 = 0ull;
#pragma unroll
            for (int e = 0; e < 8; e++) {
                u64 c2 = cb[e];
                a0 = ffma2(y2[0][e], c2, a0);
                a1 = ffma2(y2[1][e], c2, a1);
            }
#pragma unroll
            for (int e = 8; e < 16; e++) {
                u64 c2 = cb[e];
                b0 = ffma2(y2[0][e], c2, b0);
                b1 = ffma2(y2[1][e], c2, b1);
            }
            u64 s0 = fadd2(a0, b0), s1 = fadd2(a1, b1);
            int c0 = 2 * cp;
            float xlo, xhi, m;
            // branchless top-2 + SEL-based index (no predicate-guard chains)
            unpack2(xlo, xhi, s0);
            bi0 = (xlo > bv1_0) ? c0 : bi0;
            m = fminf(bv1_0, xlo); bv1_0 = fmaxf(bv1_0, xlo); bv2_0 = fmaxf(bv2_0, m);
            bi0 = (xhi > bv1_0) ? c0 + 1 : bi0;
            m = fminf(bv1_0, xhi); bv1_0 = fmaxf(bv1_0, xhi); bv2_0 = fmaxf(bv2_0, m);
            unpack2(xlo, xhi, s1);
            bi1 = (xlo > bv1_1) ? c0 : bi1;
            m = fminf(bv1_1, xlo); bv1_1 = fmaxf(bv1_1, xlo); bv2_1 = fmaxf(bv2_1, m);
            bi1 = (xhi > bv1_1) ? c0 + 1 : bi1;
            m = fminf(bv1_1, xhi); bv1_1 = fmaxf(bv1_1, xhi); bv2_1 = fmaxf(bv2_1, m);
        }

        __syncthreads();
        if (ch < 7) {
            float4* d2 = (float4*)buf[pb ^ 1];
            d2[tid] = pf0;       d2[tid + 256] = pf1;
            d2[tid + 512] = pf2; d2[tid + 768] = pf3;
            __syncthreads();
        }
    }

    sv1[warp][lane][0] = bv1_0; sv1[warp][lane][1] = bv1_1;
    sv2[warp][lane][0] = bv2_0; sv2[warp][lane][1] = bv2_1;
    six[warp][lane][0] = bi0;   six[warp][lane][1] = bi1;
    __syncthreads();

    if (warp == 0) {
#pragma unroll
        for (int rr = 0; rr < 2; rr++) {
            float v1 = NEGINF, v2 = NEGINF;
            int i1 = 0;
#pragma unroll
            for (int w = 0; w < 8; w++) {
                float a = sv1[w][lane][rr];
                int  ia = six[w][lane][rr];
                float b = sv2[w][lane][rr];
                if (a > v1 || (a == v1 && ia < i1)) {
                    v2 = fmaxf(v2, v1); v1 = a; i1 = ia;
                } else {
                    v2 = fmaxf(v2, a);
                }
                v2 = fmaxf(v2, b);
            }
            int id = (r0 + rr) * Hdim + h;
            out[id] = (float)i1;
            if (v1 - v2 <= TAU * ynorm[rr]) {
                int slot = atomicAdd(&g_cnt, 1);
                g_list[slot] = id;
            }
        }
    }
}

// ---------------- kernel Fix: fp64 recompute, persistent worklist scan --------
__global__ __launch_bounds__(256) void kFix(const float* __restrict__ x,
                                            const float* __restrict__ W,
                                            const float* __restrict__ cbk,
                                            float* __restrict__ out) {
    int gw = blockIdx.x * 8 + (threadIdx.x >> 5);  // global warp id (0..4095)
    int lane = threadIdx.x & 31;
    int cnt = g_cnt;

    for (int item = gw; item < cnt; item += 512 * 8) {
        int wid = g_list[item];
        int row = wid >> 3, h = wid & 7;
        const float* xr = x + (size_t)row * Ddim;

        // fp64 mean of the row
        double s = 0.0;
#pragma unroll 4
        for (int k = 0; k < 32; k++) s += (double)xr[32 * k + lane];
#pragma unroll
        for (int o = 16; o; o >>= 1) s += __shfl_xor_sync(0xffffffffu, s, o);
        double mu = s * (1.0 / 1024.0);

        // fp64 projections p[e] = sum_d (x_d - mu) * W[h][d][e]
        double acc[Edim];
#pragma unroll
        for (int e = 0; e < Edim; e++) acc[e] = 0.0;
        const float* Wh = W + (size_t)h * (Ddim * Edim);
        for (int k = 0; k < 32; k++) {
            int d = 32 * k + lane;
            double xv = (double)xr[d] - mu;
            const float* wp = Wh + d * Edim;
#pragma unroll
            for (int e = 0; e < Edim; e++) acc[e] += xv * (double)wp[e];
        }
#pragma unroll
        for (int e = 0; e < Edim; e++) {
#pragma unroll
            for (int o = 16; o; o >>= 1)
                acc[e] += __shfl_xor_sync(0xffffffffu, acc[e], o);
        }

        // fp64 sims over all codes, argmax with first-max semantics
        const float* cbh = cbk + (size_t)h * (CSdim * Edim);
        double bv = -1.0e300;
        int bi = 0;
        for (int c = lane; c < CSdim; c += 32) {
            const float* cp_ = cbh + c * Edim;
            double dot = 0.0, nn = 0.0;
#pragma unroll
            for (int e = 0; e < Edim; e++) {
                double cv = (double)cp_[e];
                dot += acc[e] * cv;
                nn  += cv * cv;
            }
            double sv = dot / sqrt(nn + 1e-12);
            if (sv > bv) { bv = sv; bi = c; }
        }
#pragma unroll
        for (int o = 16; o; o >>= 1) {
            double ov = __shfl_xor_sync(0xffffffffu, bv, o);
            int    oi = __shfl_xor_sync(0xffffffffu, bi, o);
            if (ov > bv || (ov == bv && oi < bi)) { bv = ov; bi = oi; }
        }
        if (lane == 0) out[(size_t)row * Hdim + h] = (float)bi;
    }
}

// ---------------- launch ------------------------------------------------------
extern "C" void kernel_launch(void* const* d_in, const int* in_sizes, int n_in,
                              void* d_out, int out_size) {
    const float* x   = (const float*)d_in[0];
    const float* W   = (n_in > 1) ? (const float*)d_in[1] : nullptr;
    const float* cbk = (n_in > 2) ? (const float*)d_in[2] : nullptr;
    for (int i = 0; i < n_in; i++) {
        if      (in_sizes[i] == Rdim * Ddim)         x   = (const float*)d_in[i];
        else if (in_sizes[i] == Hdim * Ddim * Edim)  W   = (const float*)d_in[i];
        else if (in_sizes[i] == Hdim * CSdim * Edim) cbk = (const float*)d_in[i];
    }
    float* out = (float*)d_out;   // [4,2048,8] indices stored as float32

    kTranspose<<<(Ddim * Jdim + 255) / 256, 256>>>(W);
    kColsum<<<1, 1024>>>();
    kCb<<<(Hdim * CSdim + 255) / 256, 256>>>(cbk);

    kernY<<<Rdim / 32, 256>>>(x);

    dim3 gs(Rdim / 64, Hdim);
    kernS<<<gs, 256>>>(out);

    kFix<<<512, 256>>>(x, W, cbk, out);
}